// round 6
// baseline (speedup 1.0000x reference)
#include <cuda_runtime.h>
#include <math.h>

#define D 64
#define MAX_E 1000000
#define MAX_N 100000
#define SCAN_CHUNK 1024
#define MAX_SB ((MAX_N + SCAN_CHUNK - 1) / SCAN_CHUNK)

// ---- device scratch (no allocations allowed) ----
__device__ __align__(16) float g_x[MAX_N * D];   // x = h + agg/(sum+eps), per layer
__device__ int g_cnt[MAX_N];                     // head degree histogram
__device__ int g_off[MAX_N + 1];                 // CSR offsets (exclusive scan)
__device__ int g_cur[MAX_N];                     // scatter cursors
__device__ int g_bsum[MAX_SB + 1];               // scan block sums
__device__ int g_spack[MAX_E];                   // packed (rel<<20)|tail, sorted by head

__device__ __forceinline__ float tanh_fast(float x) {
    float x2 = x * x;
    if (x2 > 0.16f) {                     // |x| > 0.4 : MUFU path (rare for this data)
        float t, r;
        asm("ex2.approx.f32 %0, %1;" : "=f"(t) : "f"(x * 2.885390081777927f));
        asm("rcp.approx.f32 %0, %1;" : "=f"(r) : "f"(t + 1.0f));
        return (t - 1.0f) * r;
    }
    // tanh(x) ~ x + x*x2*(c3 + x2*(c5 + x2*(c7 + x2*c9))), |x|<=0.4, abs err <4e-7
    float p = fmaf(x2, 0.02186948854f, -0.05396825397f);
    p = fmaf(x2, p, 0.13333333333f);
    p = fmaf(x2, p, -0.33333333333f);
    return fmaf(x * x2, p, x);
}

__device__ __forceinline__ float exp_fast(float x) {
    float t;
    asm("ex2.approx.f32 %0, %1;" : "=f"(t) : "f"(x * 1.4426950408889634f));
    return t;
}

// =================== CSR build (counting sort by head) ===================

__global__ void k_zero_cnt(int n) {
    int i = blockIdx.x * blockDim.x + threadIdx.x;
    if (i < n) g_cnt[i] = 0;
}

__global__ void k_hist(const int* __restrict__ heads, int E) {
    int i = blockIdx.x * blockDim.x + threadIdx.x;
    if (i < E) atomicAdd(&g_cnt[heads[i]], 1);
}

// per-1024-chunk exclusive scan; chunk total -> g_bsum[b]
__global__ void k_scan1(int n) {
    __shared__ int wsum[8];
    int base = blockIdx.x * SCAN_CHUNK;
    int t = threadIdx.x;
    int idx = base + t * 4;
    int c0 = (idx + 0 < n) ? g_cnt[idx + 0] : 0;
    int c1 = (idx + 1 < n) ? g_cnt[idx + 1] : 0;
    int c2 = (idx + 2 < n) ? g_cnt[idx + 2] : 0;
    int c3 = (idx + 3 < n) ? g_cnt[idx + 3] : 0;
    int s = c0 + c1 + c2 + c3;
    int lane = t & 31, w = t >> 5;
    int ps = s;
#pragma unroll
    for (int o = 1; o < 32; o <<= 1) {
        int v = __shfl_up_sync(0xffffffffu, ps, o);
        if (lane >= o) ps += v;
    }
    if (lane == 31) wsum[w] = ps;
    __syncthreads();
    if (t == 0) {
        int a = 0;
#pragma unroll
        for (int i = 0; i < 8; i++) { int v = wsum[i]; wsum[i] = a; a += v; }
        g_bsum[blockIdx.x] = a;
    }
    __syncthreads();
    int excl = wsum[w] + ps - s;
    if (idx + 0 < n) g_off[idx + 0] = excl;
    if (idx + 1 < n) g_off[idx + 1] = excl + c0;
    if (idx + 2 < n) g_off[idx + 2] = excl + c0 + c1;
    if (idx + 3 < n) g_off[idx + 3] = excl + c0 + c1 + c2;
}

// parallel scan of the (<=128) block sums, single block of 128 threads
__global__ void k_scan2(int nb) {
    __shared__ int ws[4];
    int t = threadIdx.x;
    int v = (t < nb) ? g_bsum[t] : 0;
    int lane = t & 31, w = t >> 5;
    int p = v;
#pragma unroll
    for (int o = 1; o < 32; o <<= 1) {
        int u = __shfl_up_sync(0xffffffffu, p, o);
        if (lane >= o) p += u;
    }
    if (lane == 31) ws[w] = p;
    __syncthreads();
    int add = 0;
#pragma unroll
    for (int i = 0; i < 4; i++) if (i < w) add += ws[i];
    p += add;
    if (t < nb) g_bsum[t] = p - v;   // exclusive
}

// add block offsets, produce final g_off + cursors; g_off[n] = E
__global__ void k_scan3(int n, int E) {
    int b = blockIdx.x;
    int add = g_bsum[b];
    int idx = b * SCAN_CHUNK + threadIdx.x * 4;
#pragma unroll
    for (int u = 0; u < 4; u++) {
        int i = idx + u;
        if (i < n) {
            int v = g_off[i] + add;
            g_off[i] = v;
            g_cur[i] = v;
        }
    }
    if (b == 0 && threadIdx.x == 0) g_off[n] = E;
}

__global__ void k_scatter(const int* __restrict__ heads,
                          const int* __restrict__ rels,
                          const int* __restrict__ tails, int E) {
    int i = blockIdx.x * blockDim.x + threadIdx.x;
    if (i >= E) return;
    int pos = atomicAdd(&g_cur[heads[i]], 1);
    g_spack[pos] = tails[i] | (rels[i] << 20);
}

// =================== misc ===================

__global__ void k_copy0(const float* __restrict__ ent, float* __restrict__ out,
                        int N, int out_stride) {
    int i = blockIdx.x * blockDim.x + threadIdx.x;
    int total = N * (D / 4);
    if (i < total) {
        int n = i >> 4, f = i & 15;
        float4 v = ((const float4*)ent)[i];
        *(float4*)(out + (size_t)n * out_stride + f * 4) = v;
    }
}

// =================== edge pass: one warp per head, CSR, no atomics =========
__global__ void __launch_bounds__(256) k_edge_csr(
        const float* __restrict__ h, int h_stride,
        const float* __restrict__ rel_emb, int N) {
    int gw = (blockIdx.x * 256 + threadIdx.x) >> 5;
    if (gw >= N) return;
    int lane = threadIdx.x & 31;
    int beg = g_off[gw], end = g_off[gw + 1];

    float2 eh = *(const float2*)(h + (size_t)gw * h_stride + lane * 2);
    float ax = 0.f, ay = 0.f, ssum = 0.f;

    int i = beg;
    for (; i + 2 <= end; i += 2) {
        int p0 = g_spack[i], p1 = g_spack[i + 1];
        int t0 = p0 & 0xFFFFF, r0 = p0 >> 20;
        int t1 = p1 & 0xFFFFF, r1 = p1 >> 20;
        float2 et0 = *(const float2*)(h + (size_t)t0 * h_stride + lane * 2);
        float2 er0 = *(const float2*)(rel_emb + r0 * D + lane * 2);
        float2 et1 = *(const float2*)(h + (size_t)t1 * h_stride + lane * 2);
        float2 er1 = *(const float2*)(rel_emb + r1 * D + lane * 2);
        float s0 = et0.x * tanh_fast(eh.x + er0.x) + et0.y * tanh_fast(eh.y + er0.y);
        float s1 = et1.x * tanh_fast(eh.x + er1.x) + et1.y * tanh_fast(eh.y + er1.y);
#pragma unroll
        for (int o = 16; o; o >>= 1) {      // two independent chains interleave
            s0 += __shfl_xor_sync(0xffffffffu, s0, o);
            s1 += __shfl_xor_sync(0xffffffffu, s1, o);
        }
        float ex0 = exp_fast(s0), ex1 = exp_fast(s1);
        ax += ex0 * et0.x + ex1 * et1.x;
        ay += ex0 * et0.y + ex1 * et1.y;
        ssum += ex0 + ex1;
    }
    if (i < end) {
        int p0 = g_spack[i];
        int t0 = p0 & 0xFFFFF, r0 = p0 >> 20;
        float2 et0 = *(const float2*)(h + (size_t)t0 * h_stride + lane * 2);
        float2 er0 = *(const float2*)(rel_emb + r0 * D + lane * 2);
        float s0 = et0.x * tanh_fast(eh.x + er0.x) + et0.y * tanh_fast(eh.y + er0.y);
#pragma unroll
        for (int o = 16; o; o >>= 1)
            s0 += __shfl_xor_sync(0xffffffffu, s0, o);
        float ex0 = exp_fast(s0);
        ax += ex0 * et0.x;
        ay += ex0 * et0.y;
        ssum += ex0;
    }

    float inv = 1.0f / (ssum + 1e-10f);
    float2 x = { eh.x + ax * inv, eh.y + ay * inv };
    *(float2*)(g_x + (size_t)gw * D + lane * 2) = x;
}

// ====== linear: out_cols = leaky(x @ W.T). 64-node block, 8x4 per thread ======
__global__ void __launch_bounds__(128) k_linear(
        const float* __restrict__ W,
        float* __restrict__ out,
        int N, int out_stride, int col_off) {
    __shared__ float Wsh[D][68];       // Wsh[k][j] = W[j*64 + k]
    __shared__ float xs[64][68];

    for (int idx = threadIdx.x; idx < D * D; idx += blockDim.x) {
        int jj = idx >> 6, kk = idx & 63;
        Wsh[kk][jj] = W[idx];
    }

    int nb = blockIdx.x * 64;
    {
        // 64 nodes x 64 floats = 1024 float4, 8 per thread
        int node = nb + (threadIdx.x >> 1);
        int base = (threadIdx.x & 1) * 32;
        float* row = xs[threadIdx.x >> 1];
        if (node < N) {
            const float* xr = g_x + (size_t)node * D;
#pragma unroll
            for (int u = 0; u < 8; u++)
                *(float4*)(row + base + u * 4) = *(const float4*)(xr + base + u * 4);
        } else {
            float4 z = {0.f, 0.f, 0.f, 0.f};
#pragma unroll
            for (int u = 0; u < 8; u++)
                *(float4*)(row + base + u * 4) = z;
        }
    }
    __syncthreads();

    int rg = threadIdx.x >> 4;          // node group 0..7 (8 nodes each)
    int c4 = (threadIdx.x & 15) * 4;    // output col group

    float4 acc[8];
#pragma unroll
    for (int i = 0; i < 8; i++) acc[i] = make_float4(0.f, 0.f, 0.f, 0.f);

#pragma unroll
    for (int kk = 0; kk < D; kk += 4) {
        float4 wv0 = *(const float4*)&Wsh[kk + 0][c4];
        float4 wv1 = *(const float4*)&Wsh[kk + 1][c4];
        float4 wv2 = *(const float4*)&Wsh[kk + 2][c4];
        float4 wv3 = *(const float4*)&Wsh[kk + 3][c4];
#pragma unroll
        for (int i = 0; i < 8; i++) {
            float4 xv = *(const float4*)&xs[rg * 8 + i][kk];
            acc[i].x = fmaf(xv.x, wv0.x, acc[i].x);
            acc[i].y = fmaf(xv.x, wv0.y, acc[i].y);
            acc[i].z = fmaf(xv.x, wv0.z, acc[i].z);
            acc[i].w = fmaf(xv.x, wv0.w, acc[i].w);
            acc[i].x = fmaf(xv.y, wv1.x, acc[i].x);
            acc[i].y = fmaf(xv.y, wv1.y, acc[i].y);
            acc[i].z = fmaf(xv.y, wv1.z, acc[i].z);
            acc[i].w = fmaf(xv.y, wv1.w, acc[i].w);
            acc[i].x = fmaf(xv.z, wv2.x, acc[i].x);
            acc[i].y = fmaf(xv.z, wv2.y, acc[i].y);
            acc[i].z = fmaf(xv.z, wv2.z, acc[i].z);
            acc[i].w = fmaf(xv.z, wv2.w, acc[i].w);
            acc[i].x = fmaf(xv.w, wv3.x, acc[i].x);
            acc[i].y = fmaf(xv.w, wv3.y, acc[i].y);
            acc[i].z = fmaf(xv.w, wv3.z, acc[i].z);
            acc[i].w = fmaf(xv.w, wv3.w, acc[i].w);
        }
    }

#pragma unroll
    for (int i = 0; i < 8; i++) {
        int n = nb + rg * 8 + i;
        if (n < N) {
            float4 v = acc[i];
            v.x = v.x > 0.f ? v.x : 0.2f * v.x;
            v.y = v.y > 0.f ? v.y : 0.2f * v.y;
            v.z = v.z > 0.f ? v.z : 0.2f * v.z;
            v.w = v.w > 0.f ? v.w : 0.2f * v.w;
            *(float4*)(out + (size_t)n * out_stride + col_off + c4) = v;
        }
    }
}

extern "C" void kernel_launch(void* const* d_in, const int* in_sizes, int n_in,
                              void* d_out, int out_size) {
    const int*   heads      = (const int*)d_in[0];
    const int*   rels       = (const int*)d_in[1];
    const int*   tails      = (const int*)d_in[2];
    const float* ent        = (const float*)d_in[3];
    const float* rel_embeds = (const float*)d_in[4];
    const float* Ws         = (const float*)d_in[5];
    float*       out        = (float*)d_out;

    int E = in_sizes[0];
    int N = in_sizes[3] / D;
    int L = in_sizes[5] / (D * D);
    int NREL = (L > 0) ? in_sizes[4] / (L * D) : 0;
    int out_stride = D * (L + 1);
    int SB = (N + SCAN_CHUNK - 1) / SCAN_CHUNK;

    // --- CSR build (once per call) ---
    k_zero_cnt<<<(N + 255) / 256, 256>>>(N);
    k_hist<<<(E + 255) / 256, 256>>>(heads, E);
    k_scan1<<<SB, 256>>>(N);
    k_scan2<<<1, 128>>>(SB);
    k_scan3<<<SB, 256>>>(N, E);
    k_scatter<<<(E + 255) / 256, 256>>>(heads, rels, tails, E);

    // layer-0 output columns
    k_copy0<<<(N * (D / 4) + 255) / 256, 256>>>(ent, out, N, out_stride);

    int eblocks = (N * 32 + 255) / 256;       // warp per head
    int lblocks = (N + 63) / 64;

    const float* hcur = ent;
    int hstride = D;

    for (int l = 0; l < L; l++) {
        k_edge_csr<<<eblocks, 256>>>(hcur, hstride,
                                     rel_embeds + (size_t)l * NREL * D, N);
        k_linear<<<lblocks, 128>>>(Ws + (size_t)l * D * D, out,
                                   N, out_stride, (l + 1) * D);
        hcur = out + (size_t)(l + 1) * D;
        hstride = out_stride;
    }
}